// round 5
// baseline (speedup 1.0000x reference)
#include <cuda_runtime.h>
#include <cuda_bf16.h>
#include <math.h>

// Eikonal loss, single fused kernel. One thread = one 4-pixel group,
// 10 fully independent loads (max MLP), no rolling windows, no shuffles.
// (B,1,H,W) = (64,1,512,512) fp32 -> 1 fp32 scalar.

#define H 512
#define W 512
#define W4 (W / 4)
#define THREADS 256
#define MAX_BLOCKS 16384

__device__ float2 g_part[MAX_BLOCKS];
__device__ unsigned int g_ticket;   // zero-init at load; last block resets it

__device__ __forceinline__ float sqrt_approx(float x) {
    float r;
    asm("sqrt.approx.f32 %0, %1;" : "=f"(r) : "f"(x));
    return r;
}

__global__ void __launch_bounds__(THREADS) eik_fused_kernel(
    const float* __restrict__ pred,
    const float* __restrict__ reach,
    float* __restrict__ out,
    int nBlocks)
{
    const int gid = blockIdx.x * THREADS + threadIdx.x;
    // gid -> (b, y, x4): all powers of two, pure bit ops
    const int x4 = gid & (W4 - 1);
    const int y  = (gid >> 7) & (H - 1);
    const int b  = gid >> 16;

    const int x  = x4 * 4;
    const int xl = (x > 0) ? (x - 1) : 0;
    const int xr = (x + 4 < W) ? (x + 4) : (W - 1);
    const int yT = (y > 0) ? (y - 1) : 0;
    const int yB = (y < H - 1) ? (y + 1) : (H - 1);

    const size_t base = (size_t)b * (H * W);
    const float* rowT = pred + base + (size_t)yT * W;
    const float* rowM = pred + base + (size_t)y  * W;
    const float* rowB = pred + base + (size_t)yB * W;

    // --- 10 independent loads ---
    float4 vT = *(const float4*)(rowT + x);
    float4 vM = *(const float4*)(rowM + x);
    float4 vB = *(const float4*)(rowB + x);
    float tL = __ldg(rowT + xl), tR = __ldg(rowT + xr);
    float mL = __ldg(rowM + xl), mR = __ldg(rowM + xr);
    float bL = __ldg(rowB + xl), bR = __ldg(rowB + xr);
    float4 rr = *(const float4*)(reach + base + (size_t)y * W + x);

    const float t[6]  = {tL, vT.x, vT.y, vT.z, vT.w, tR};
    const float m[6]  = {mL, vM.x, vM.y, vM.z, vM.w, mR};
    const float bt[6] = {bL, vB.x, vB.y, vB.z, vB.w, bR};
    const float rv[4] = {rr.x, rr.y, rr.z, rr.w};

    float lsum = 0.0f;
    float lcnt = 0.0f;

    #pragma unroll
    for (int j = 0; j < 4; j++) {
        // cross-correlation with Sobel/8
        float gx = (t[j + 2] - t[j]) + 2.0f * (m[j + 2] - m[j]) + (bt[j + 2] - bt[j]);
        float gy = (bt[j] + 2.0f * bt[j + 1] + bt[j + 2]) - (t[j] + 2.0f * t[j + 1] + t[j + 2]);
        gx *= 0.125f;
        gy *= 0.125f;
        float g2   = fmaf(gx, gx, fmaf(gy, gy, 1e-8f));
        float viol = fabsf(sqrt_approx(g2) - 1.0f);
        float msk  = (rv[j] > 0.5f) ? 1.0f : 0.0f;
        lsum = fmaf(viol, msk, lsum);
        lcnt += msk;
    }

    // ---- block reduction (8 warps) ----
    #pragma unroll
    for (int off = 16; off > 0; off >>= 1) {
        lsum += __shfl_down_sync(0xFFFFFFFFu, lsum, off);
        lcnt += __shfl_down_sync(0xFFFFFFFFu, lcnt, off);
    }

    __shared__ float s_sum[8];
    __shared__ float s_cnt[8];
    const int lane = threadIdx.x & 31;
    const int wid  = threadIdx.x >> 5;
    if (lane == 0) { s_sum[wid] = lsum; s_cnt[wid] = lcnt; }
    __syncthreads();

    __shared__ bool s_last;
    if (wid == 0) {
        lsum = (lane < 8) ? s_sum[lane] : 0.0f;
        lcnt = (lane < 8) ? s_cnt[lane] : 0.0f;
        #pragma unroll
        for (int off = 4; off > 0; off >>= 1) {
            lsum += __shfl_down_sync(0xFFFFFFFFu, lsum, off);
            lcnt += __shfl_down_sync(0xFFFFFFFFu, lcnt, off);
        }
        if (lane == 0) {
            g_part[blockIdx.x] = make_float2(lsum, lcnt);
            __threadfence();
            unsigned int prev = atomicAdd(&g_ticket, 1u);
            s_last = (prev == (unsigned int)(nBlocks - 1));
        }
    }
    __syncthreads();

    // ---- last block: reduce partials, write output, reset ticket ----
    if (s_last) {
        float fs = 0.0f, fc = 0.0f;
        for (int i = threadIdx.x; i < nBlocks; i += THREADS) {
            float2 v = g_part[i];
            fs += v.x;
            fc += v.y;
        }
        #pragma unroll
        for (int off = 16; off > 0; off >>= 1) {
            fs += __shfl_down_sync(0xFFFFFFFFu, fs, off);
            fc += __shfl_down_sync(0xFFFFFFFFu, fc, off);
        }
        if (lane == 0) { s_sum[wid] = fs; s_cnt[wid] = fc; }
        __syncthreads();
        if (threadIdx.x == 0) {
            fs = 0.0f; fc = 0.0f;
            #pragma unroll
            for (int i = 0; i < 8; i++) { fs += s_sum[i]; fc += s_cnt[i]; }
            out[0] = fs / fmaxf(fc, 1.0f);
            g_ticket = 0;   // reset for next graph replay
        }
    }
}

extern "C" void kernel_launch(void* const* d_in, const int* in_sizes, int n_in,
                              void* d_out, int out_size) {
    const float* pred  = (const float*)d_in[0];
    const float* reach = (const float*)d_in[1];
    float* out = (float*)d_out;

    const int total   = in_sizes[0];              // B*H*W
    const int nBlocks = (total / 4) / THREADS;    // 16384 for B=64

    eik_fused_kernel<<<nBlocks, THREADS>>>(pred, reach, out, nBlocks);
}

// round 6
// speedup vs baseline: 1.0476x; 1.0476x over previous
#include <cuda_runtime.h>
#include <cuda_bf16.h>
#include <math.h>

// Eikonal loss, single fused kernel.
// One thread = two vertically adjacent 4-px groups (rows y, y+1).
// Halos via warp shuffle; only warp-edge lanes do (predicated) scalar loads.
// (B,1,H,W) = (64,1,512,512) fp32 -> 1 fp32 scalar.

#define H 512
#define W 512
#define W4 (W / 4)
#define THREADS 256
#define MAX_BLOCKS 16384

__device__ float2 g_part[MAX_BLOCKS];
__device__ unsigned int g_ticket;   // zero-init at load; last block resets it

__device__ __forceinline__ float sqrt_approx(float x) {
    float r;
    asm("sqrt.approx.f32 %0, %1;" : "=f"(r) : "f"(x));
    return r;
}

// From a row's float4 + shfl halos, produce scaled horizontal diff D and
// vertical-kernel row sum S for 4 pixels.
__device__ __forceinline__ void row_sd(float4 v, const float* __restrict__ row,
                                       int x, int lane,
                                       float* __restrict__ S,
                                       float* __restrict__ D) {
    float wl = __shfl_up_sync(0xFFFFFFFFu, v.w, 1);
    float wr = __shfl_down_sync(0xFFFFFFFFu, v.x, 1);
    if (lane == 0)  wl = (x == 0)       ? v.x : __ldg(row + x - 1);
    if (lane == 31) wr = (x + 4 >= W)   ? v.w : __ldg(row + x + 4);
    D[0] = (v.y - wl)  * 0.125f;
    D[1] = (v.z - v.x) * 0.125f;
    D[2] = (v.w - v.y) * 0.125f;
    D[3] = (wr  - v.z) * 0.125f;
    S[0] = fmaf(2.0f, v.x, wl  + v.y) * 0.125f;
    S[1] = fmaf(2.0f, v.y, v.x + v.z) * 0.125f;
    S[2] = fmaf(2.0f, v.z, v.y + v.w) * 0.125f;
    S[3] = fmaf(2.0f, v.w, v.z + wr ) * 0.125f;
}

__global__ void __launch_bounds__(THREADS) eik_fused_kernel(
    const float* __restrict__ pred,
    const float* __restrict__ reach,
    float* __restrict__ out,
    int nBlocks)
{
    const int gid  = blockIdx.x * THREADS + threadIdx.x;
    const int lane = threadIdx.x & 31;
    // gid -> (b, ypair, x4): powers of two, bit ops only
    const int x4 = gid & (W4 - 1);
    const int yp = (gid >> 7) & (H / 2 - 1);
    const int b  = gid >> 15;

    const int x = x4 * 4;
    const int y = yp * 2;

    const size_t base = (size_t)b * (H * W);
    const float* p = pred + base;

    // 4 pred rows for 2 output rows: y-1, y, y+1, y+2 (edge-clamped)
    const float* r0 = p + (size_t)((y > 0) ? (y - 1) : 0) * W;
    const float* r1 = p + (size_t)y * W;
    const float* r2 = r1 + W;
    const float* r3 = p + (size_t)((y + 2 < H) ? (y + 2) : (H - 1)) * W;

    // --- independent loads ---
    float4 v0 = *(const float4*)(r0 + x);
    float4 v1 = *(const float4*)(r1 + x);
    float4 v2 = *(const float4*)(r2 + x);
    float4 v3 = *(const float4*)(r3 + x);
    float4 ra = *(const float4*)(reach + base + (size_t)y * W + x);
    float4 rb = *(const float4*)(reach + base + (size_t)(y + 1) * W + x);

    float S0[4], S1[4], S2[4], S3[4];
    float D0[4], D1[4], D2[4], D3[4];
    row_sd(v0, r0, x, lane, S0, D0);
    row_sd(v1, r1, x, lane, S1, D1);
    row_sd(v2, r2, x, lane, S2, D2);
    row_sd(v3, r3, x, lane, S3, D3);

    const float rva[4] = {ra.x, ra.y, ra.z, ra.w};
    const float rvb[4] = {rb.x, rb.y, rb.z, rb.w};

    float lsum = 0.0f;
    float lcnt = 0.0f;

    #pragma unroll
    for (int j = 0; j < 4; j++) {
        // output row y: rows (0,1,2)
        float gx = fmaf(2.0f, D1[j], D0[j] + D2[j]);
        float gy = S2[j] - S0[j];
        float g2 = fmaf(gx, gx, fmaf(gy, gy, 1e-8f));
        float viol = fabsf(sqrt_approx(g2) - 1.0f);
        float msk  = (rva[j] > 0.5f) ? 1.0f : 0.0f;
        lsum = fmaf(viol, msk, lsum);
        lcnt += msk;
    }
    #pragma unroll
    for (int j = 0; j < 4; j++) {
        // output row y+1: rows (1,2,3)
        float gx = fmaf(2.0f, D2[j], D1[j] + D3[j]);
        float gy = S3[j] - S1[j];
        float g2 = fmaf(gx, gx, fmaf(gy, gy, 1e-8f));
        float viol = fabsf(sqrt_approx(g2) - 1.0f);
        float msk  = (rvb[j] > 0.5f) ? 1.0f : 0.0f;
        lsum = fmaf(viol, msk, lsum);
        lcnt += msk;
    }

    // ---- block reduction (8 warps) ----
    #pragma unroll
    for (int off = 16; off > 0; off >>= 1) {
        lsum += __shfl_down_sync(0xFFFFFFFFu, lsum, off);
        lcnt += __shfl_down_sync(0xFFFFFFFFu, lcnt, off);
    }

    __shared__ float s_sum[8];
    __shared__ float s_cnt[8];
    const int wid = threadIdx.x >> 5;
    if (lane == 0) { s_sum[wid] = lsum; s_cnt[wid] = lcnt; }
    __syncthreads();

    __shared__ bool s_last;
    if (wid == 0) {
        lsum = (lane < 8) ? s_sum[lane] : 0.0f;
        lcnt = (lane < 8) ? s_cnt[lane] : 0.0f;
        #pragma unroll
        for (int off = 4; off > 0; off >>= 1) {
            lsum += __shfl_down_sync(0xFFFFFFFFu, lsum, off);
            lcnt += __shfl_down_sync(0xFFFFFFFFu, lcnt, off);
        }
        if (lane == 0) {
            g_part[blockIdx.x] = make_float2(lsum, lcnt);
            __threadfence();
            unsigned int prev = atomicAdd(&g_ticket, 1u);
            s_last = (prev == (unsigned int)(nBlocks - 1));
        }
    }
    __syncthreads();

    // ---- last block: reduce partials, write output, reset ticket ----
    if (s_last) {
        float fs = 0.0f, fc = 0.0f;
        for (int i = threadIdx.x; i < nBlocks; i += THREADS) {
            float2 v = g_part[i];
            fs += v.x;
            fc += v.y;
        }
        #pragma unroll
        for (int off = 16; off > 0; off >>= 1) {
            fs += __shfl_down_sync(0xFFFFFFFFu, fs, off);
            fc += __shfl_down_sync(0xFFFFFFFFu, fc, off);
        }
        if (lane == 0) { s_sum[wid] = fs; s_cnt[wid] = fc; }
        __syncthreads();
        if (threadIdx.x == 0) {
            fs = 0.0f; fc = 0.0f;
            #pragma unroll
            for (int i = 0; i < 8; i++) { fs += s_sum[i]; fc += s_cnt[i]; }
            out[0] = fs / fmaxf(fc, 1.0f);
            g_ticket = 0;   // reset for next graph replay
        }
    }
}

extern "C" void kernel_launch(void* const* d_in, const int* in_sizes, int n_in,
                              void* d_out, int out_size) {
    const float* pred  = (const float*)d_in[0];
    const float* reach = (const float*)d_in[1];
    float* out = (float*)d_out;

    const int total   = in_sizes[0];              // B*H*W
    const int nBlocks = (total / 8) / THREADS;    // 8192 for B=64

    eik_fused_kernel<<<nBlocks, THREADS>>>(pred, reach, out, nBlocks);
}

// round 7
// speedup vs baseline: 1.3773x; 1.3147x over previous
#include <cuda_runtime.h>
#include <cuda_bf16.h>
#include <math.h>

// Eikonal loss, single fused kernel.
// One thread = 4x4 pixel item (4 rows x 4 cols). 6 pred rows + 4 reach rows,
// all loads independent & up-front. Halos via warp shuffle. Streaming loads
// for reach. (B,1,H,W) = (64,1,512,512) fp32 -> 1 fp32 scalar.

#define H 512
#define W 512
#define W4 (W / 4)
#define THREADS 256
#define MAX_BLOCKS 16384

__device__ float2 g_part[MAX_BLOCKS];
__device__ unsigned int g_ticket;   // zero-init at load; last block resets it

__device__ __forceinline__ float sqrt_approx(float x) {
    float r;
    asm("sqrt.approx.f32 %0, %1;" : "=f"(r) : "f"(x));
    return r;
}

// From a row's float4 + shfl halos, produce scaled horizontal diff D and
// vertical-kernel row sum S for 4 pixels.
__device__ __forceinline__ void row_sd(float4 v, const float* __restrict__ row,
                                       int x, int lane,
                                       float* __restrict__ S,
                                       float* __restrict__ D) {
    float wl = __shfl_up_sync(0xFFFFFFFFu, v.w, 1);
    float wr = __shfl_down_sync(0xFFFFFFFFu, v.x, 1);
    if (lane == 0)  wl = (x == 0)       ? v.x : __ldg(row + x - 1);
    if (lane == 31) wr = (x + 4 >= W)   ? v.w : __ldg(row + x + 4);
    D[0] = (v.y - wl)  * 0.125f;
    D[1] = (v.z - v.x) * 0.125f;
    D[2] = (v.w - v.y) * 0.125f;
    D[3] = (wr  - v.z) * 0.125f;
    S[0] = fmaf(2.0f, v.x, wl  + v.y) * 0.125f;
    S[1] = fmaf(2.0f, v.y, v.x + v.z) * 0.125f;
    S[2] = fmaf(2.0f, v.z, v.y + v.w) * 0.125f;
    S[3] = fmaf(2.0f, v.w, v.z + wr ) * 0.125f;
}

__global__ void __launch_bounds__(THREADS, 4) eik_fused_kernel(
    const float* __restrict__ pred,
    const float* __restrict__ reach,
    float* __restrict__ out,
    int nBlocks)
{
    const int gid  = blockIdx.x * THREADS + threadIdx.x;
    const int lane = threadIdx.x & 31;
    // gid -> (b, yquad, x4): powers of two, bit ops only
    const int x4 = gid & (W4 - 1);
    const int yq = (gid >> 7) & (H / 4 - 1);
    const int b  = gid >> 14;

    const int x = x4 * 4;
    const int y = yq * 4;

    const size_t base = (size_t)b * (H * W);
    const float* p = pred + base;
    const float* r = reach + base;

    // 6 pred rows for 4 output rows: y-1 .. y+4 (edge-clamped)
    const float* pr0 = p + (size_t)((y > 0) ? (y - 1) : 0) * W;
    const float* pr1 = p + (size_t)y * W;
    const float* pr2 = pr1 + W;
    const float* pr3 = pr2 + W;
    const float* pr4 = pr3 + W;
    const float* pr5 = p + (size_t)((y + 4 < H) ? (y + 4) : (H - 1)) * W;

    // --- all loads independent, issued up-front ---
    float4 v0 = *(const float4*)(pr0 + x);
    float4 v1 = *(const float4*)(pr1 + x);
    float4 v2 = *(const float4*)(pr2 + x);
    float4 v3 = *(const float4*)(pr3 + x);
    float4 v4 = *(const float4*)(pr4 + x);
    float4 v5 = *(const float4*)(pr5 + x);
    float4 ra = __ldcs((const float4*)(r + (size_t)(y + 0) * W + x));
    float4 rb = __ldcs((const float4*)(r + (size_t)(y + 1) * W + x));
    float4 rc = __ldcs((const float4*)(r + (size_t)(y + 2) * W + x));
    float4 rd = __ldcs((const float4*)(r + (size_t)(y + 3) * W + x));

    float S[6][4], D[6][4];
    row_sd(v0, pr0, x, lane, S[0], D[0]);
    row_sd(v1, pr1, x, lane, S[1], D[1]);
    row_sd(v2, pr2, x, lane, S[2], D[2]);
    row_sd(v3, pr3, x, lane, S[3], D[3]);
    row_sd(v4, pr4, x, lane, S[4], D[4]);
    row_sd(v5, pr5, x, lane, S[5], D[5]);

    const float rv[4][4] = {{ra.x, ra.y, ra.z, ra.w},
                            {rb.x, rb.y, rb.z, rb.w},
                            {rc.x, rc.y, rc.z, rc.w},
                            {rd.x, rd.y, rd.z, rd.w}};

    float lsum = 0.0f;
    float lcnt = 0.0f;

    #pragma unroll
    for (int i = 0; i < 4; i++) {
        #pragma unroll
        for (int j = 0; j < 4; j++) {
            float gx = fmaf(2.0f, D[i + 1][j], D[i][j] + D[i + 2][j]);
            float gy = S[i + 2][j] - S[i][j];
            float g2 = fmaf(gx, gx, fmaf(gy, gy, 1e-8f));
            float viol = fabsf(sqrt_approx(g2) - 1.0f);
            float msk  = (rv[i][j] > 0.5f) ? 1.0f : 0.0f;
            lsum = fmaf(viol, msk, lsum);
            lcnt += msk;
        }
    }

    // ---- block reduction (8 warps) ----
    #pragma unroll
    for (int off = 16; off > 0; off >>= 1) {
        lsum += __shfl_down_sync(0xFFFFFFFFu, lsum, off);
        lcnt += __shfl_down_sync(0xFFFFFFFFu, lcnt, off);
    }

    __shared__ float s_sum[8];
    __shared__ float s_cnt[8];
    const int wid = threadIdx.x >> 5;
    if (lane == 0) { s_sum[wid] = lsum; s_cnt[wid] = lcnt; }
    __syncthreads();

    __shared__ bool s_last;
    if (wid == 0) {
        lsum = (lane < 8) ? s_sum[lane] : 0.0f;
        lcnt = (lane < 8) ? s_cnt[lane] : 0.0f;
        #pragma unroll
        for (int off = 4; off > 0; off >>= 1) {
            lsum += __shfl_down_sync(0xFFFFFFFFu, lsum, off);
            lcnt += __shfl_down_sync(0xFFFFFFFFu, lcnt, off);
        }
        if (lane == 0) {
            g_part[blockIdx.x] = make_float2(lsum, lcnt);
            __threadfence();
            unsigned int prev = atomicAdd(&g_ticket, 1u);
            s_last = (prev == (unsigned int)(nBlocks - 1));
        }
    }
    __syncthreads();

    // ---- last block: reduce partials, write output, reset ticket ----
    if (s_last) {
        float fs = 0.0f, fc = 0.0f;
        for (int i = threadIdx.x; i < nBlocks; i += THREADS) {
            float2 v = g_part[i];
            fs += v.x;
            fc += v.y;
        }
        #pragma unroll
        for (int off = 16; off > 0; off >>= 1) {
            fs += __shfl_down_sync(0xFFFFFFFFu, fs, off);
            fc += __shfl_down_sync(0xFFFFFFFFu, fc, off);
        }
        if (lane == 0) { s_sum[wid] = fs; s_cnt[wid] = fc; }
        __syncthreads();
        if (threadIdx.x == 0) {
            fs = 0.0f; fc = 0.0f;
            #pragma unroll
            for (int i = 0; i < 8; i++) { fs += s_sum[i]; fc += s_cnt[i]; }
            out[0] = fs / fmaxf(fc, 1.0f);
            g_ticket = 0;   // reset for next graph replay
        }
    }
}

extern "C" void kernel_launch(void* const* d_in, const int* in_sizes, int n_in,
                              void* d_out, int out_size) {
    const float* pred  = (const float*)d_in[0];
    const float* reach = (const float*)d_in[1];
    float* out = (float*)d_out;

    const int total   = in_sizes[0];              // B*H*W
    const int nBlocks = (total / 16) / THREADS;   // 4096 for B=64

    eik_fused_kernel<<<nBlocks, THREADS>>>(pred, reach, out, nBlocks);
}